// round 3
// baseline (speedup 1.0000x reference)
#include <cuda_runtime.h>

#define BB 2
#define FF 32
#define NN 1024
#define HH 64

// Scratch: [b][hslot][n], hslot 0..63 = Hi (with b1 folded in), 64..127 = Hj
__device__ float g_H[BB * 128 * NN];

__device__ __forceinline__ float sigmoidf_fast(float x) {
    return __fdividef(1.0f, 1.0f + __expf(-x));
}

// ---------------------------------------------------------------------------
// Phase 1: Hi[b,h,n] = sum_f emb[b,f,n]*W1[h,f] + b1[h]
//          Hj[b,h,n] = sum_f emb[b,f,n]*W1[h,F+f]
// grid = BB*(NN/16) blocks, 128 threads (t = hslot)
// ---------------------------------------------------------------------------
__global__ void __launch_bounds__(128) phase1_kernel(
    const float* __restrict__ emb,  // [B][F][N]
    const float* __restrict__ W1,   // [H][2F]
    const float* __restrict__ b1)   // [H]
{
    const int t   = threadIdx.x;        // 0..127 = hslot
    const int h   = t & 63;
    const int isj = t >> 6;
    const int blk = blockIdx.x;
    const int b   = blk / (NN / 16);
    const int n0  = (blk % (NN / 16)) * 16;

    __shared__ float es[FF][16];        // e tile: es[f][n]

    // cooperative load of emb tile: 32x16 floats = 128 float4, 1 per thread
    {
        int f  = t >> 2;
        int n4 = t & 3;
        *(float4*)&es[f][n4 * 4] =
            *(const float4*)&emb[(b * FF + f) * NN + n0 + n4 * 4];
    }

    float w[FF];
    #pragma unroll
    for (int f = 0; f < FF; f++)
        w[f] = W1[h * (2 * FF) + isj * FF + f];
    const float bias = isj ? 0.0f : b1[h];

    __syncthreads();

    float* outp = &g_H[(size_t)(b * 128 + t) * NN + n0];
    #pragma unroll
    for (int n4 = 0; n4 < 4; n4++) {
        float a0 = bias, a1 = bias, a2 = bias, a3 = bias;
        #pragma unroll
        for (int f = 0; f < FF; f++) {
            float4 ev = *(float4*)&es[f][n4 * 4];   // broadcast across warp
            a0 = fmaf(ev.x, w[f], a0);
            a1 = fmaf(ev.y, w[f], a1);
            a2 = fmaf(ev.z, w[f], a2);
            a3 = fmaf(ev.w, w[f], a3);
        }
        float4 r = {a0, a1, a2, a3};
        *(float4*)&outp[n4 * 4] = r;
    }
}

// ---------------------------------------------------------------------------
// Phase 2: out[b,i,j] = sigmoid( sum_h relu(Hi[b,i,h]+Hj[b,j,h]) * W2[h] + b2 )
// 64x64 output tile per block, 256 threads, 4x4 register blocking.
// Shared tiles are h-major (his[h][i]) so LDS.128 along i/j is conflict-free.
// ---------------------------------------------------------------------------
__global__ void __launch_bounds__(256) phase2_kernel(
    const float* __restrict__ W2,   // [1][H]
    const float* __restrict__ b2,   // [1]
    float* __restrict__ out)        // [B][N][N]
{
    __shared__ float his[HH][64];
    __shared__ float hjs[HH][64];
    __shared__ float w2s[HH];

    const int tid = threadIdx.x;
    const int b   = blockIdx.z;
    const int i0  = blockIdx.y * 64;
    const int j0  = blockIdx.x * 64;

    const float* Hi = &g_H[(size_t)(b * 128) * NN];
    const float* Hj = &g_H[(size_t)(b * 128 + 64) * NN];

    // load tiles: 64h x 64 floats each, as float4
    #pragma unroll
    for (int idx = tid; idx < HH * 16; idx += 256) {
        int h  = idx >> 4;
        int c4 = idx & 15;
        *(float4*)&his[h][c4 * 4] = *(const float4*)&Hi[h * NN + i0 + c4 * 4];
        *(float4*)&hjs[h][c4 * 4] = *(const float4*)&Hj[h * NN + j0 + c4 * 4];
    }
    if (tid < HH) w2s[tid] = W2[tid];
    __syncthreads();

    const int tx = tid & 15;   // i-subtile
    const int ty = tid >> 4;   // j-subtile

    float acc[4][4] = {};

    #pragma unroll 8
    for (int h = 0; h < HH; h++) {
        float4 hi4 = *(float4*)&his[h][tx * 4];
        float4 hj4 = *(float4*)&hjs[h][ty * 4];
        float wv   = w2s[h];
        float hiv[4] = {hi4.x, hi4.y, hi4.z, hi4.w};
        float hjv[4] = {hj4.x, hj4.y, hj4.z, hj4.w};
        #pragma unroll
        for (int a = 0; a < 4; a++) {
            #pragma unroll
            for (int c = 0; c < 4; c++) {
                float s = hiv[a] + hjv[c];
                s = fmaxf(s, 0.0f);
                acc[a][c] = fmaf(s, wv, acc[a][c]);
            }
        }
    }

    const float b2v = b2[0];
    #pragma unroll
    for (int a = 0; a < 4; a++) {
        float4 r;
        r.x = sigmoidf_fast(acc[a][0] + b2v);
        r.y = sigmoidf_fast(acc[a][1] + b2v);
        r.z = sigmoidf_fast(acc[a][2] + b2v);
        r.w = sigmoidf_fast(acc[a][3] + b2v);
        size_t row = (size_t)(b * NN + i0 + tx * 4 + a) * NN;
        *(float4*)&out[row + j0 + ty * 4] = r;
    }
}

// ---------------------------------------------------------------------------
// inputs (metadata order): 0=adj_in (unused), 1=emb_in, 2=layer (unused),
//                          3=W1, 4=b1, 5=W2, 6=b2
// ---------------------------------------------------------------------------
extern "C" void kernel_launch(void* const* d_in, const int* in_sizes, int n_in,
                              void* d_out, int out_size)
{
    const float* emb = (const float*)d_in[1];
    const float* W1  = (const float*)d_in[3];
    const float* b1  = (const float*)d_in[4];
    const float* W2  = (const float*)d_in[5];
    const float* b2  = (const float*)d_in[6];
    float* out = (float*)d_out;

    phase1_kernel<<<BB * (NN / 16), 128>>>(emb, W1, b1);

    dim3 grid(NN / 64, NN / 64, BB);
    phase2_kernel<<<grid, 256>>>(W2, b2, out);
}

// round 4
// speedup vs baseline: 1.0765x; 1.0765x over previous
#include <cuda_runtime.h>

#define BB 2
#define FF 32
#define NN 1024
#define HH 64

// Scratch: [b][hslot][n], hslot 0..63 = Hi (with b1 folded in), 64..127 = Hj
__device__ float g_H[BB * 128 * NN];

__device__ __forceinline__ float sigmoidf_fast(float x) {
    return __fdividef(1.0f, 1.0f + __expf(-x));
}

// ---------------------------------------------------------------------------
// Phase 1: Hi[b,h,n] = sum_f emb[b,f,n]*W1[h,f] + b1[h]
//          Hj[b,h,n] = sum_f emb[b,f,n]*W1[h,F+f]
// grid = BB*(NN/16) blocks, 128 threads (t = hslot)
// ---------------------------------------------------------------------------
__global__ void __launch_bounds__(128) phase1_kernel(
    const float* __restrict__ emb,  // [B][F][N]
    const float* __restrict__ W1,   // [H][2F]
    const float* __restrict__ b1)   // [H]
{
    const int t   = threadIdx.x;        // 0..127 = hslot
    const int h   = t & 63;
    const int isj = t >> 6;
    const int blk = blockIdx.x;
    const int b   = blk / (NN / 16);
    const int n0  = (blk % (NN / 16)) * 16;

    __shared__ float es[FF][16];        // e tile: es[f][n]

    // cooperative load of emb tile: 32x16 floats = 128 float4, 1 per thread
    {
        int f  = t >> 2;
        int n4 = t & 3;
        *(float4*)&es[f][n4 * 4] =
            *(const float4*)&emb[(b * FF + f) * NN + n0 + n4 * 4];
    }

    float w[FF];
    #pragma unroll
    for (int f = 0; f < FF; f++)
        w[f] = W1[h * (2 * FF) + isj * FF + f];
    const float bias = isj ? 0.0f : b1[h];

    __syncthreads();

    float* outp = &g_H[(size_t)(b * 128 + t) * NN + n0];
    #pragma unroll
    for (int n4 = 0; n4 < 4; n4++) {
        float a0 = bias, a1 = bias, a2 = bias, a3 = bias;
        #pragma unroll
        for (int f = 0; f < FF; f++) {
            float4 ev = *(float4*)&es[f][n4 * 4];   // broadcast across warp
            a0 = fmaf(ev.x, w[f], a0);
            a1 = fmaf(ev.y, w[f], a1);
            a2 = fmaf(ev.z, w[f], a2);
            a3 = fmaf(ev.w, w[f], a3);
        }
        float4 r = {a0, a1, a2, a3};
        *(float4*)&outp[n4 * 4] = r;
    }
}

// ---------------------------------------------------------------------------
// Phase 2: out[b,i,j] = sigmoid( sum_h relu(Hi[b,i,h]+Hj[b,j,h]) * W2[h] + b2 )
// 64x64 output tile per block, 256 threads, 4x4 register blocking.
// Shared tiles are h-major (his[h][i]) so LDS.128 along i/j is conflict-free.
// ---------------------------------------------------------------------------
__global__ void __launch_bounds__(256) phase2_kernel(
    const float* __restrict__ W2,   // [1][H]
    const float* __restrict__ b2,   // [1]
    float* __restrict__ out)        // [B][N][N]
{
    __shared__ float his[HH][64];
    __shared__ float hjs[HH][64];
    __shared__ float w2s[HH];

    const int tid = threadIdx.x;
    const int b   = blockIdx.z;
    const int i0  = blockIdx.y * 64;
    const int j0  = blockIdx.x * 64;

    const float* Hi = &g_H[(size_t)(b * 128) * NN];
    const float* Hj = &g_H[(size_t)(b * 128 + 64) * NN];

    // load tiles: 64h x 64 floats each, as float4
    #pragma unroll
    for (int idx = tid; idx < HH * 16; idx += 256) {
        int h  = idx >> 4;
        int c4 = idx & 15;
        *(float4*)&his[h][c4 * 4] = *(const float4*)&Hi[h * NN + i0 + c4 * 4];
        *(float4*)&hjs[h][c4 * 4] = *(const float4*)&Hj[h * NN + j0 + c4 * 4];
    }
    if (tid < HH) w2s[tid] = W2[tid];
    __syncthreads();

    const int tx = tid & 15;   // i-subtile
    const int ty = tid >> 4;   // j-subtile

    float acc[4][4] = {};

    #pragma unroll 8
    for (int h = 0; h < HH; h++) {
        float4 hi4 = *(float4*)&his[h][tx * 4];
        float4 hj4 = *(float4*)&hjs[h][ty * 4];
        float wv   = w2s[h];
        float hiv[4] = {hi4.x, hi4.y, hi4.z, hi4.w};
        float hjv[4] = {hj4.x, hj4.y, hj4.z, hj4.w};
        #pragma unroll
        for (int a = 0; a < 4; a++) {
            #pragma unroll
            for (int c = 0; c < 4; c++) {
                float s = hiv[a] + hjv[c];
                s = fmaxf(s, 0.0f);
                acc[a][c] = fmaf(s, wv, acc[a][c]);
            }
        }
    }

    const float b2v = b2[0];
    #pragma unroll
    for (int a = 0; a < 4; a++) {
        float4 r;
        r.x = sigmoidf_fast(acc[a][0] + b2v);
        r.y = sigmoidf_fast(acc[a][1] + b2v);
        r.z = sigmoidf_fast(acc[a][2] + b2v);
        r.w = sigmoidf_fast(acc[a][3] + b2v);
        size_t row = (size_t)(b * NN + i0 + tx * 4 + a) * NN;
        *(float4*)&out[row + j0 + ty * 4] = r;
    }
}

// ---------------------------------------------------------------------------
// inputs (metadata order): 0=adj_in (unused), 1=emb_in, 2=layer (unused),
//                          3=W1, 4=b1, 5=W2, 6=b2
// ---------------------------------------------------------------------------
extern "C" void kernel_launch(void* const* d_in, const int* in_sizes, int n_in,
                              void* d_out, int out_size)
{
    const float* emb = (const float*)d_in[1];
    const float* W1  = (const float*)d_in[3];
    const float* b1  = (const float*)d_in[4];
    const float* W2  = (const float*)d_in[5];
    const float* b2  = (const float*)d_in[6];
    float* out = (float*)d_out;

    phase1_kernel<<<BB * (NN / 16), 128>>>(emb, W1, b1);

    dim3 grid(NN / 64, NN / 64, BB);
    phase2_kernel<<<grid, 256>>>(W2, b2, out);
}

// round 5
// speedup vs baseline: 1.1582x; 1.0759x over previous
#include <cuda_runtime.h>

#define BB 2
#define FF 32
#define NN 1024
#define HH 64
#define TI 32
#define TJ 64

// Scratch: [b][hslot][n], hslot 0..63 = Hi (with b1 folded in), 64..127 = Hj
__device__ float g_H[BB * 128 * NN];

__device__ __forceinline__ float sigmoidf_fast(float x) {
    return __fdividef(1.0f, 1.0f + __expf(-x));
}

// packed step: acc2 += max(hid2 + hj2, 0) * w2   (element-wise on f32x2)
#define EDGE_STEP(ACC, HID, HJ2, W2)                                   \
    asm("{\n\t"                                                        \
        ".reg .b64 s;\n\t"                                             \
        ".reg .f32 sl, sh;\n\t"                                        \
        "add.rn.f32x2 s, %1, %2;\n\t"                                  \
        "mov.b64 {sl, sh}, s;\n\t"                                     \
        "max.f32 sl, sl, 0f00000000;\n\t"                              \
        "max.f32 sh, sh, 0f00000000;\n\t"                              \
        "mov.b64 s, {sl, sh};\n\t"                                     \
        "fma.rn.f32x2 %0, s, %3, %0;\n\t"                              \
        "}" : "+l"(ACC) : "l"(HID), "l"(HJ2), "l"(W2))

#define DUP2(D, S)                                                     \
    asm("mov.b64 %0, {%1, %1};" : "=l"(D) : "f"(S))

#define UNPACK2(LO, HI, S)                                             \
    asm("mov.b64 {%0, %1}, %2;" : "=f"(LO), "=f"(HI) : "l"(S))

// ---------------------------------------------------------------------------
// Phase 1: Hi[b,h,n] = sum_f emb[b,f,n]*W1[h,f] + b1[h]
//          Hj[b,h,n] = sum_f emb[b,f,n]*W1[h,F+f]
// ---------------------------------------------------------------------------
__global__ void __launch_bounds__(128) phase1_kernel(
    const float* __restrict__ emb,  // [B][F][N]
    const float* __restrict__ W1,   // [H][2F]
    const float* __restrict__ b1)   // [H]
{
    const int t   = threadIdx.x;        // 0..127 = hslot
    const int h   = t & 63;
    const int isj = t >> 6;
    const int blk = blockIdx.x;
    const int b   = blk / (NN / 16);
    const int n0  = (blk % (NN / 16)) * 16;

    __shared__ float es[FF][16];

    {
        int f  = t >> 2;
        int n4 = t & 3;
        *(float4*)&es[f][n4 * 4] =
            *(const float4*)&emb[(b * FF + f) * NN + n0 + n4 * 4];
    }

    float w[FF];
    #pragma unroll
    for (int f = 0; f < FF; f++)
        w[f] = W1[h * (2 * FF) + isj * FF + f];
    const float bias = isj ? 0.0f : b1[h];

    __syncthreads();

    float* outp = &g_H[(size_t)(b * 128 + t) * NN + n0];
    #pragma unroll
    for (int n4 = 0; n4 < 4; n4++) {
        float a0 = bias, a1 = bias, a2 = bias, a3 = bias;
        #pragma unroll
        for (int f = 0; f < FF; f++) {
            float4 ev = *(float4*)&es[f][n4 * 4];
            a0 = fmaf(ev.x, w[f], a0);
            a1 = fmaf(ev.y, w[f], a1);
            a2 = fmaf(ev.z, w[f], a2);
            a3 = fmaf(ev.w, w[f], a3);
        }
        float4 r = {a0, a1, a2, a3};
        *(float4*)&outp[n4 * 4] = r;
    }
}

// ---------------------------------------------------------------------------
// Phase 2: out[b,i,j] = sigmoid( sum_h relu(Hi[b,i,h]+Hj[b,j,h]) * W2[h] + b2 )
// 32x64 (i,j) tile per block, 256 threads, 2i x 4j per thread, j packed f32x2.
// __launch_bounds__(256,6) -> <=42 regs -> 6 blocks/SM, grid=1024 (6.9/SM).
// ---------------------------------------------------------------------------
__global__ void __launch_bounds__(256, 6) phase2_kernel(
    const float* __restrict__ W2,   // [1][H]
    const float* __restrict__ b2,   // [1]
    float* __restrict__ out)        // [B][N][N]
{
    __shared__ float his[HH][TI];                  // 8 KB
    __shared__ float hjs[HH][TJ];                  // 16 KB
    __shared__ unsigned long long w2d[HH];         // 512 B (w duplicated pairs)

    const int tid = threadIdx.x;
    const int b   = blockIdx.z;
    const int i0  = blockIdx.y * TI;
    const int j0  = blockIdx.x * TJ;

    const float* Hi = &g_H[(size_t)(b * 128) * NN];
    const float* Hj = &g_H[(size_t)(b * 128 + 64) * NN];

    // his: 64h x 32 floats = 512 float4
    #pragma unroll
    for (int idx = tid; idx < HH * (TI / 4); idx += 256) {
        int h  = idx >> 3;
        int c4 = idx & 7;
        *(float4*)&his[h][c4 * 4] = *(const float4*)&Hi[h * NN + i0 + c4 * 4];
    }
    // hjs: 64h x 64 floats = 1024 float4
    #pragma unroll
    for (int idx = tid; idx < HH * (TJ / 4); idx += 256) {
        int h  = idx >> 4;
        int c4 = idx & 15;
        *(float4*)&hjs[h][c4 * 4] = *(const float4*)&Hj[h * NN + j0 + c4 * 4];
    }
    if (tid < HH) {
        float w = W2[tid];
        unsigned long long wp;
        DUP2(wp, w);
        w2d[tid] = wp;
    }
    __syncthreads();

    const int tx = tid & 15;   // j-subtile: 4 j's = 2 packed pairs
    const int ty = tid >> 4;   // i-subtile: 2 i's

    unsigned long long acc[2][2] = {0ull, 0ull, 0ull, 0ull};

    #pragma unroll 16
    for (int h = 0; h < HH; h++) {
        float2 hi2 = *(float2*)&his[h][ty * 2];            // LDS.64 (broadcast)
        unsigned long long hid0, hid1;
        DUP2(hid0, hi2.x);
        DUP2(hid1, hi2.y);
        ulonglong2 hj = *(ulonglong2*)&hjs[h][tx * 4];     // LDS.128
        unsigned long long w2 = w2d[h];                    // LDS.64 broadcast

        EDGE_STEP(acc[0][0], hid0, hj.x, w2);
        EDGE_STEP(acc[0][1], hid0, hj.y, w2);
        EDGE_STEP(acc[1][0], hid1, hj.x, w2);
        EDGE_STEP(acc[1][1], hid1, hj.y, w2);
    }

    const float b2v = b2[0];
    #pragma unroll
    for (int r = 0; r < 2; r++) {
        float a0, a1, a2, a3;
        UNPACK2(a0, a1, acc[r][0]);
        UNPACK2(a2, a3, acc[r][1]);
        float4 o;
        o.x = sigmoidf_fast(a0 + b2v);
        o.y = sigmoidf_fast(a1 + b2v);
        o.z = sigmoidf_fast(a2 + b2v);
        o.w = sigmoidf_fast(a3 + b2v);
        size_t row = (size_t)(b * NN + i0 + ty * 2 + r) * NN;
        *(float4*)&out[row + j0 + tx * 4] = o;
    }
}

// ---------------------------------------------------------------------------
// inputs (metadata order): 0=adj_in (unused), 1=emb_in, 2=layer (unused),
//                          3=W1, 4=b1, 5=W2, 6=b2
// ---------------------------------------------------------------------------
extern "C" void kernel_launch(void* const* d_in, const int* in_sizes, int n_in,
                              void* d_out, int out_size)
{
    const float* emb = (const float*)d_in[1];
    const float* W1  = (const float*)d_in[3];
    const float* b1  = (const float*)d_in[4];
    const float* W2  = (const float*)d_in[5];
    const float* b2  = (const float*)d_in[6];
    float* out = (float*)d_out;

    phase1_kernel<<<BB * (NN / 16), 128>>>(emb, W1, b1);

    dim3 grid(NN / TJ, NN / TI, BB);
    phase2_kernel<<<grid, 256>>>(W2, b2, out);
}

// round 6
// speedup vs baseline: 1.1868x; 1.0246x over previous
#include <cuda_runtime.h>

#define BB 2
#define FF 32
#define NN 1024
#define HH 64
#define TI 32
#define TJ 64

// Scratch: [b][hslot][n], hslot 0..63 = Hi (with b1 folded in), 64..127 = Hj
__device__ float g_H[BB * 128 * NN];

__device__ __forceinline__ float sigmoidf_fast(float x) {
    return __fdividef(1.0f, 1.0f + __expf(-x));
}

// packed step: acc2 += max(hid2 + hj2, 0) * w2   (element-wise on f32x2)
#define EDGE_STEP(ACC, HID, HJ2, W2)                                   \
    asm("{\n\t"                                                        \
        ".reg .b64 s;\n\t"                                             \
        ".reg .f32 sl, sh;\n\t"                                        \
        "add.rn.f32x2 s, %1, %2;\n\t"                                  \
        "mov.b64 {sl, sh}, s;\n\t"                                     \
        "max.f32 sl, sl, 0f00000000;\n\t"                              \
        "max.f32 sh, sh, 0f00000000;\n\t"                              \
        "mov.b64 s, {sl, sh};\n\t"                                     \
        "fma.rn.f32x2 %0, s, %3, %0;\n\t"                              \
        "}" : "+l"(ACC) : "l"(HID), "l"(HJ2), "l"(W2))

#define DUP2(D, S)                                                     \
    asm("mov.b64 %0, {%1, %1};" : "=l"(D) : "f"(S))

#define UNPACK2(LO, HI, S)                                             \
    asm("mov.b64 {%0, %1}, %2;" : "=f"(LO), "=f"(HI) : "l"(S))

// ---------------------------------------------------------------------------
// Phase 1: Hi[b,h,n] = sum_f emb[b,f,n]*W1[h,f] + b1[h]
//          Hj[b,h,n] = sum_f emb[b,f,n]*W1[h,F+f]
// ---------------------------------------------------------------------------
__global__ void __launch_bounds__(128) phase1_kernel(
    const float* __restrict__ emb,  // [B][F][N]
    const float* __restrict__ W1,   // [H][2F]
    const float* __restrict__ b1)   // [H]
{
    const int t   = threadIdx.x;        // 0..127 = hslot
    const int h   = t & 63;
    const int isj = t >> 6;
    const int blk = blockIdx.x;
    const int b   = blk / (NN / 16);
    const int n0  = (blk % (NN / 16)) * 16;

    __shared__ float es[FF][16];

    {
        int f  = t >> 2;
        int n4 = t & 3;
        *(float4*)&es[f][n4 * 4] =
            *(const float4*)&emb[(b * FF + f) * NN + n0 + n4 * 4];
    }

    float w[FF];
    #pragma unroll
    for (int f = 0; f < FF; f++)
        w[f] = W1[h * (2 * FF) + isj * FF + f];
    const float bias = isj ? 0.0f : b1[h];

    __syncthreads();

    float* outp = &g_H[(size_t)(b * 128 + t) * NN + n0];
    #pragma unroll
    for (int n4 = 0; n4 < 4; n4++) {
        float a0 = bias, a1 = bias, a2 = bias, a3 = bias;
        #pragma unroll
        for (int f = 0; f < FF; f++) {
            float4 ev = *(float4*)&es[f][n4 * 4];
            a0 = fmaf(ev.x, w[f], a0);
            a1 = fmaf(ev.y, w[f], a1);
            a2 = fmaf(ev.z, w[f], a2);
            a3 = fmaf(ev.w, w[f], a3);
        }
        float4 r = {a0, a1, a2, a3};
        *(float4*)&outp[n4 * 4] = r;
    }
}

// ---------------------------------------------------------------------------
// Phase 2: out[b,i,j] = sigmoid( sum_h relu(Hi[b,i,h]+Hj[b,j,h]) * W2[h] + b2 )
// 32x64 (i,j) tile per block, 256 threads, 2i x 4j per thread, j packed f32x2.
// __launch_bounds__(256,6) -> <=42 regs -> 6 blocks/SM, grid=1024 (6.9/SM).
// ---------------------------------------------------------------------------
__global__ void __launch_bounds__(256, 6) phase2_kernel(
    const float* __restrict__ W2,   // [1][H]
    const float* __restrict__ b2,   // [1]
    float* __restrict__ out)        // [B][N][N]
{
    __shared__ float his[HH][TI];                  // 8 KB
    __shared__ float hjs[HH][TJ];                  // 16 KB
    __shared__ unsigned long long w2d[HH];         // 512 B (w duplicated pairs)

    const int tid = threadIdx.x;
    const int b   = blockIdx.z;
    const int i0  = blockIdx.y * TI;
    const int j0  = blockIdx.x * TJ;

    const float* Hi = &g_H[(size_t)(b * 128) * NN];
    const float* Hj = &g_H[(size_t)(b * 128 + 64) * NN];

    // his: 64h x 32 floats = 512 float4
    #pragma unroll
    for (int idx = tid; idx < HH * (TI / 4); idx += 256) {
        int h  = idx >> 3;
        int c4 = idx & 7;
        *(float4*)&his[h][c4 * 4] = *(const float4*)&Hi[h * NN + i0 + c4 * 4];
    }
    // hjs: 64h x 64 floats = 1024 float4
    #pragma unroll
    for (int idx = tid; idx < HH * (TJ / 4); idx += 256) {
        int h  = idx >> 4;
        int c4 = idx & 15;
        *(float4*)&hjs[h][c4 * 4] = *(const float4*)&Hj[h * NN + j0 + c4 * 4];
    }
    if (tid < HH) {
        float w = W2[tid];
        unsigned long long wp;
        DUP2(wp, w);
        w2d[tid] = wp;
    }
    __syncthreads();

    const int tx = tid & 15;   // j-subtile: 4 j's = 2 packed pairs
    const int ty = tid >> 4;   // i-subtile: 2 i's

    unsigned long long acc[2][2] = {0ull, 0ull, 0ull, 0ull};

    #pragma unroll 16
    for (int h = 0; h < HH; h++) {
        float2 hi2 = *(float2*)&his[h][ty * 2];            // LDS.64 (broadcast)
        unsigned long long hid0, hid1;
        DUP2(hid0, hi2.x);
        DUP2(hid1, hi2.y);
        ulonglong2 hj = *(ulonglong2*)&hjs[h][tx * 4];     // LDS.128
        unsigned long long w2 = w2d[h];                    // LDS.64 broadcast

        EDGE_STEP(acc[0][0], hid0, hj.x, w2);
        EDGE_STEP(acc[0][1], hid0, hj.y, w2);
        EDGE_STEP(acc[1][0], hid1, hj.x, w2);
        EDGE_STEP(acc[1][1], hid1, hj.y, w2);
    }

    const float b2v = b2[0];
    #pragma unroll
    for (int r = 0; r < 2; r++) {
        float a0, a1, a2, a3;
        UNPACK2(a0, a1, acc[r][0]);
        UNPACK2(a2, a3, acc[r][1]);
        float4 o;
        o.x = sigmoidf_fast(a0 + b2v);
        o.y = sigmoidf_fast(a1 + b2v);
        o.z = sigmoidf_fast(a2 + b2v);
        o.w = sigmoidf_fast(a3 + b2v);
        size_t row = (size_t)(b * NN + i0 + ty * 2 + r) * NN;
        *(float4*)&out[row + j0 + tx * 4] = o;
    }
}

// ---------------------------------------------------------------------------
// inputs (metadata order): 0=adj_in (unused), 1=emb_in, 2=layer (unused),
//                          3=W1, 4=b1, 5=W2, 6=b2
// ---------------------------------------------------------------------------
extern "C" void kernel_launch(void* const* d_in, const int* in_sizes, int n_in,
                              void* d_out, int out_size)
{
    const float* emb = (const float*)d_in[1];
    const float* W1  = (const float*)d_in[3];
    const float* b1  = (const float*)d_in[4];
    const float* W2  = (const float*)d_in[5];
    const float* b2  = (const float*)d_in[6];
    float* out = (float*)d_out;

    phase1_kernel<<<BB * (NN / 16), 128>>>(emb, W1, b1);

    dim3 grid(NN / TJ, NN / TI, BB);
    phase2_kernel<<<grid, 256>>>(W2, b2, out);
}